// round 17
// baseline (speedup 1.0000x reference)
#include <cuda_runtime.h>
#include <math.h>

#define NN 8
#define HH 12
#define DHD 64
#define LV 1568
#define LA 512
#define NCV 392
#define NCA 256
#define NHNH (NN*HH)          // 96
#define OSTR 5696             // output row stride
#define RS_V 8
#define RS_A 8
#define SCALEF 0.125f

#define K1_BLOCKS (2 * RS_V * NHNH)   // 1536
#define K2_BLOCKS (RS_A * NHNH)       // 768
#define K3_BLOCKS (2 * NHNH)          // 192
#define SUM_BLOCKS NN                 // 8
#define FILL_BLOCKS (4 * NN)          // 32
#define TOK_PER_N (NCV + NCA)         // 648
#define KP_BLOCKS (TOK_PER_N / 8)     // 81 (8 warps/block, warp-per-token)

// ---- scratch (device globals; no allocation allowed) ----
// Partials laid out [n][col][h][y]: the 96 partials of one (n,col) are 384
// contiguous bytes -> consumer reads them with one float4 per lane (lanes 0..23).
__device__ float g_sum_av[NN];
__device__ float g_sum_va[NN];
__device__ __align__(16) float g_vpos[NN * LV * HH * RS_V];
__device__ __align__(16) float g_apos[NN * LA * HH * RS_A];

// KBIG: five block families, all depending only on kernel inputs:
//  [0, K1)            : v_pos partials from cross_av (float4 row reads)
//  [K1, +K2)          : a_pos partials from cross_va (float2 row reads)
//  [+K3)              : cls weighted means (in-block weight gather + sum)
//  [+SUM)             : g_sum_av / g_sum_va for kp
//  [+FILL)            : output defaults (prob=0, prune=n_attn)
__global__ void kbig(const float* __restrict__ cross_av,
                     const float* __restrict__ cross_va,
                     const float* __restrict__ pos_v_q,
                     const float* __restrict__ pos_a_q,
                     const int* __restrict__ ids_a,
                     const int* __restrict__ ids_v,
                     const float* __restrict__ n_attn_av,
                     const float* __restrict__ n_attn_va,
                     float* __restrict__ out) {
    const int bid = blockIdx.x;
    const int t = threadIdx.x;   // 256
    __shared__ __align__(16) char smem_raw[4608];

    if (bid < K1_BLOCKS) {
        int* ridx = (int*)smem_raw;                 // 32
        float* rw = (float*)(smem_raw + 128);       // 32
        const int x = bid & 1;
        const int y = (bid >> 1) & (RS_V - 1);
        const int nh = bid >> 4;
        const int n = nh / HH;
        const int h = nh % HH;
        const int g = x * 256 + t;
        const int RPB = NCA / RS_V;                 // 32

        if (t < RPB) {
            int a = y * RPB + t;
            int id = ids_a[n * LA + a];
            ridx[t] = id;
            rw[t]   = n_attn_va[n * LA + id];
        }
        __syncthreads();
        if (g >= LV / 4) return;

        float4 acc = make_float4(0.f, 0.f, 0.f, 0.f);
        const float4* base = (const float4*)cross_av;
        const size_t nhbase = (size_t)nh * LA * (LV / 4);
#pragma unroll 8
        for (int a = 0; a < RPB; a++) {
            float w = rw[a];
            float4 v = __ldg(base + nhbase + (size_t)ridx[a] * (LV / 4) + g);
            acc.x += w * v.x; acc.y += w * v.y; acc.z += w * v.z; acc.w += w * v.w;
        }
        // [n][col][h][y] scatter: 4 cols, stride 96 floats (L2-resident buffer)
        float* dst = g_vpos + ((size_t)(n * LV + 4 * g) * HH + h) * RS_V + y;
        dst[0 * HH * RS_V] = acc.x;
        dst[1 * HH * RS_V] = acc.y;
        dst[2 * HH * RS_V] = acc.z;
        dst[3 * HH * RS_V] = acc.w;
    } else if (bid < K1_BLOCKS + K2_BLOCKS) {
        int* ridx = (int*)smem_raw;                 // 49
        float* rw = (float*)(smem_raw + 256);       // 49
        const int b2 = bid - K1_BLOCKS;
        const int y = b2 & (RS_A - 1);
        const int nh = b2 >> 3;
        const int n = nh / HH;
        const int h = nh % HH;
        const int RPB = NCV / RS_A;                 // 49

        if (t < RPB) {
            int v = y * RPB + t;
            int id = ids_v[n * LV + v];
            ridx[t] = id;
            rw[t]   = n_attn_av[n * LV + id];
        }
        __syncthreads();

        float2 acc = make_float2(0.f, 0.f);
        const float2* base = (const float2*)cross_va;
        const size_t nhbase = (size_t)nh * LV * (LA / 2);
#pragma unroll 7
        for (int a = 0; a < RPB; a++) {
            float w = rw[a];
            float2 v = __ldg(base + nhbase + (size_t)ridx[a] * (LA / 2) + t);
            acc.x += w * v.x; acc.y += w * v.y;
        }
        float* dst = g_apos + ((size_t)(n * LA + 2 * t) * HH + h) * RS_A + y;
        dst[0 * HH * RS_A] = acc.x;
        dst[1 * HH * RS_A] = acc.y;
    } else if (bid < K1_BLOCKS + K2_BLOCKS + K3_BLOCKS) {
        // cls: weighted mean over gathered rows of pos_*_q (in-block weight sum)
        int* ridx = (int*)smem_raw;                       // up to 392 ints
        float* rw = (float*)(smem_raw + 1600);            // up to 392 floats
        float* part = (float*)(smem_raw + 3200);          // 4*64 floats
        float* wred = (float*)(smem_raw + 4224);          // 8 warp sums
        const int b3 = bid - (K1_BLOCKS + K2_BLOCKS);
        const int nh = b3 >> 1;
        const bool vside = (b3 & 1) == 0;
        const int n = nh / HH;
        const int h = nh % HH;
        const int d = t & 63;
        const int sub = t >> 6;   // 0..3

        const int cnt = vside ? NCV : NCA;
        const int L = vside ? LV : LA;
        const int* ids = vside ? ids_v : ids_a;
        const float* attn = vside ? n_attn_av : n_attn_va;
        const float* q = vside ? pos_v_q : pos_a_q;

        float lsum = 0.f;
        for (int i = t; i < cnt; i += 256) {
            int id = ids[n * L + i];
            float w = attn[n * L + id];
            ridx[i] = id;
            rw[i]   = w;
            lsum += w;
        }
#pragma unroll
        for (int s = 16; s > 0; s >>= 1) lsum += __shfl_xor_sync(0xffffffff, lsum, s);
        if ((t & 31) == 0) wred[t >> 5] = lsum;
        __syncthreads();

        float acc = 0.f;
        const float* basep = q + (size_t)nh * L * DHD;
#pragma unroll 8
        for (int i = sub; i < cnt; i += 4)
            acc += __ldg(basep + (size_t)ridx[i] * DHD + d) * rw[i];

        part[sub * DHD + d] = acc;
        __syncthreads();

        if (sub == 0) {
            float tot = acc + part[DHD + d] + part[2 * DHD + d] + part[3 * DHD + d];
            float su = 0.f;
#pragma unroll
            for (int w8 = 0; w8 < 8; w8++) su += wred[w8];
            const int off = vside ? 2080 : 2848;
            out[n * OSTR + off + h * DHD + d] = tot / su;
        }
    } else if (bid < K1_BLOCKS + K2_BLOCKS + K3_BLOCKS + SUM_BLOCKS) {
        // sums of gathered weights for kp
        float* red = (float*)smem_raw;   // 256 floats
        const int n = bid - (K1_BLOCKS + K2_BLOCKS + K3_BLOCKS);

        float sv = 0.f;
        for (int i = t; i < NCV; i += 256) {
            int id = ids_v[n * LV + i];
            sv += n_attn_av[n * LV + id];
        }
        red[t] = sv;
        __syncthreads();
        for (int s = 128; s > 0; s >>= 1) {
            if (t < s) red[t] += red[t + s];
            __syncthreads();
        }
        if (t == 0) g_sum_av[n] = red[0];
        __syncthreads();

        float sa = 0.f;
        for (int i = t; i < NCA; i += 256) {
            int id = ids_a[n * LA + i];
            sa += n_attn_va[n * LA + id];
        }
        red[t] = sa;
        __syncthreads();
        for (int s = 128; s > 0; s >>= 1) {
            if (t < s) red[t] += red[t + s];
            __syncthreads();
        }
        if (t == 0) g_sum_va[n] = red[0];
    } else {
        // output defaults
        const int b5 = bid - (K1_BLOCKS + K2_BLOCKS + K3_BLOCKS + SUM_BLOCKS);
        const int n = b5 >> 2;
        const int p = b5 & 3;
        float* o = out + n * OSTR;
        for (int i = p * 256 + t; i < LV + LA; i += 1024) o[i] = 0.f;
        for (int i = p * 256 + t; i < LV; i += 1024) o[3616 + i] = n_attn_av[n * LV + i];
        for (int i = p * 256 + t; i < LA; i += 1024) o[5184 + i] = n_attn_va[n * LA + i];
    }
}

// KP: warp-per-token, no block barriers. grid (81, NN), 256 threads = 8 warps.
// Warp handles one (n, token) across ALL 12 heads:
//   prologue: 12 cls float2 + 12 K-row float2 + lanes<24 one float4 of partials (MLP~25)
//   12 shfl-reduce chains; lanes 2h/2h+1 inject head-h's partial correction;
//   prob accumulates in-register (shfl_xor leaves sum in every lane).
__global__ void kp_prob(const float* __restrict__ pos_v_k,
                        const float* __restrict__ pos_a_k,
                        const float* __restrict__ spu_a_cls,
                        const float* __restrict__ spu_v_cls,
                        const int* __restrict__ ids_v,
                        const int* __restrict__ ids_a,
                        const float* __restrict__ u_v,
                        const float* __restrict__ u_a,
                        const float* __restrict__ n_attn_av,
                        const float* __restrict__ n_attn_va,
                        float* __restrict__ out) {
    const int n = blockIdx.y;
    const int wid = threadIdx.x >> 5;
    const int lane = threadIdx.x & 31;
    const int tk = blockIdx.x * 8 + wid;          // 0..647
    const bool vside = (tk < NCV);
    const int token = vside ? tk : tk - NCV;

    const int L = vside ? LV : LA;
    const int* ids = vside ? ids_v : ids_a;
    const float* kk = vside ? pos_v_k : pos_a_k;
    const float* cls = vside ? spu_a_cls : spu_v_cls;
    const float* gposn = (vside ? g_vpos + (size_t)n * LV * (HH * RS_V)
                                : g_apos + (size_t)n * LA * (HH * RS_A));

    const int row = __ldg(&ids[n * L + token]);
    const float inv = vside ? (1.f / g_sum_va[n]) : (1.f / g_sum_av[n]);

    // Prologue loads (independent)
    float2 c2[HH], r2[HH];
    const float2* clsb = (const float2*)(cls + (size_t)n * HH * DHD);
    const float2* kb = (const float2*)(kk + (size_t)n * HH * L * DHD);
#pragma unroll
    for (int h = 0; h < HH; h++) {
        c2[h] = __ldg(clsb + (size_t)h * (DHD / 2) + lane);
        r2[h] = __ldg(kb + ((size_t)h * L + row) * (DHD / 2) + lane);
    }
    float gpc = 0.f;   // lane's share of head (lane>>1)'s partial sum, pre-scaled
    if (lane < 24) {
        float4 g4 = __ldg((const float4*)(gposn + (size_t)row * (HH * RS_V)) + lane);
        gpc = (g4.x + g4.y + g4.z + g4.w) * inv;
    }

    // 12 independent reduce chains; accumulate head-mean in-register
    float prob = 0.f;
#pragma unroll
    for (int h = 0; h < HH; h++) {
        float val = (r2[h].x * c2[h].x + r2[h].y * c2[h].y) * SCALEF;
        if ((lane >> 1) == h) val -= gpc;
#pragma unroll
        for (int s = 16; s > 0; s >>= 1) val += __shfl_xor_sync(0xffffffff, val, s);
        prob += 1.f / (1.f + __expf(-val));     // sigmoid(spu - vp), sum in all lanes
    }
    prob *= (1.f / HH);

    if (lane == 0) {
        float* o = out + n * OSTR;
        if (vside) {
            o[row] = prob;
            float uu = __ldg(&u_v[n * LV + row]);
            o[3616 + row] = (uu < prob) ? 0.f : __ldg(&n_attn_av[n * LV + row]);
        } else {
            o[1568 + row] = prob;
            float uu = __ldg(&u_a[n * LA + row]);
            o[5184 + row] = (uu < prob) ? 0.f : __ldg(&n_attn_va[n * LA + row]);
        }
    }
}

extern "C" void kernel_launch(void* const* d_in, const int* in_sizes, int n_in,
                              void* d_out, int out_size) {
    const float* pos_v_q   = (const float*)d_in[0];
    const float* pos_v_k   = (const float*)d_in[1];
    const float* pos_a_q   = (const float*)d_in[2];
    const float* pos_a_k   = (const float*)d_in[3];
    const float* cross_av  = (const float*)d_in[4];
    const float* cross_va  = (const float*)d_in[5];
    const float* n_attn_av = (const float*)d_in[6];
    const float* n_attn_va = (const float*)d_in[7];
    const float* spu_a_cls = (const float*)d_in[8];
    const float* spu_v_cls = (const float*)d_in[9];
    const float* u_v       = (const float*)d_in[10];
    const float* u_a       = (const float*)d_in[11];
    const int*   ids_v     = (const int*)d_in[12];
    const int*   ids_a     = (const int*)d_in[13];
    float* out = (float*)d_out;

    kbig<<<K1_BLOCKS + K2_BLOCKS + K3_BLOCKS + SUM_BLOCKS + FILL_BLOCKS, 256>>>(
        cross_av, cross_va, pos_v_q, pos_a_q, ids_a, ids_v,
        n_attn_av, n_attn_va, out);
    kp_prob<<<dim3(KP_BLOCKS, NN), 256>>>(pos_v_k, pos_a_k, spu_a_cls, spu_v_cls,
                                          ids_v, ids_a, u_v, u_a,
                                          n_attn_av, n_attn_va, out);
}